// round 10
// baseline (speedup 1.0000x reference)
#include <cuda_runtime.h>
#include <math.h>

#define NN 4000
#define NE 60000

typedef unsigned long long u64;

// ---------------- scratch ----------------
__device__ float g_WA[2][4096];   // Ws@Wa per set
__device__ float g_WTA[2][4096];  // Wt@Wa per set
__device__ float g_WeA[2][2048];  // We@Wa per set
__device__ float g_Ut[2][512];    // [set][hd][h]  (Wv·Wo folded)
__device__ float g_G[2][256];     // [set][hd][ce] = Ut @ We^T
__device__ float g_A[NN * 3072];  // [n][part][16][64]; part 0=As set0,1=As set1,2=At own
__device__ float g_Y3[NN * 576];  // [n][part][3][64]; part 0=Ys set0,1=Ys set1,2=Yt own
__device__ float g_eexp[NE * 8];  // exp(logit)
__device__ float g_expsum[NN * 8];
__device__ int   g_mask[NN];

struct ParSet {
    const float *emb_s, *emb_t, *w_d, *We, *Ws, *Wt, *Wa, *va, *Wv, *Wo;
};
struct Par2 { ParSet s[2]; };

// ---------------- packed f32x2 helpers (FFMA2/FADD2: 2x fp32 throughput) ----------------
__device__ __forceinline__ u64 pk2(float a) {
    u64 r;
    asm("mov.b64 %0, {%1, %1};" : "=l"(r) : "r"(__float_as_uint(a)));
    return r;
}
__device__ __forceinline__ u64 fma2(u64 a, u64 b, u64 c) {
    u64 d;
    asm("fma.rn.f32x2 %0, %1, %2, %3;" : "=l"(d) : "l"(a), "l"(b), "l"(c));
    return d;
}
__device__ __forceinline__ u64 add2(u64 a, u64 b) {
    u64 d;
    asm("add.rn.f32x2 %0, %1, %2;" : "=l"(d) : "l"(a), "l"(b));
    return d;
}
__device__ __forceinline__ u64 d2l(double d) { return __double_as_longlong(d); }
__device__ __forceinline__ float2 up2(u64 v) {
    float2 f;
    asm("mov.b64 {%0, %1}, %2;" : "=f"(f.x), "=f"(f.y) : "l"(v));
    return f;
}

// ---------------- weight folds + zeroing + mask sniff (block 64) ----------------
__global__ void k_small(Par2 P, const void* nm, float* out) {
    if (blockIdx.x == 64) {
        __shared__ int s_max, s_s1;
        if (threadIdx.x == 0) { s_max = 0; s_s1 = 0; }
        __syncthreads();
        const unsigned char* bp = (const unsigned char*)nm;
        int lm = 0, ls = 0;
        for (int i = threadIdx.x; i < NN; i += 256) {
            int v = bp[i];
            if (v > lm) lm = v;
            if ((i & 3) == 1) ls += v;
        }
        atomicMax(&s_max, lm);
        atomicAdd(&s_s1, ls);
        __syncthreads();
        int mode = (s_max > 1) ? 2 : (s_s1 > 0 ? 0 : 1);
        for (int n = threadIdx.x; n < NN; n += 256) {
            int v;
            if (mode == 0)      v = (bp[n] != 0);
            else if (mode == 1) v = (((const int*)nm)[n] != 0);
            else                v = (((const float*)nm)[n] != 0.0f);
            g_mask[n] = v;
        }
        return;
    }
    int tid = blockIdx.x * blockDim.x + threadIdx.x;
    const int stride = 64 * 256;
    for (int i = tid; i < 16384; i += stride) {
        int mat = i >> 12, c = (i >> 6) & 63, j = i & 63;
        int set = mat & 1;
        const float* W  = (mat < 2) ? P.s[set].Ws : P.s[set].Wt;
        const float* Wa = P.s[set].Wa;
        float s = 0.0f;
        for (int h = 0; h < 64; h++) s += W[c * 64 + h] * Wa[h * 64 + j];
        if (mat < 2) g_WA[set][c * 64 + j] = s;
        else         g_WTA[set][c * 64 + j] = s;
    }
    for (int i = tid; i < 4096; i += stride) {
        int set = i >> 11, ce = (i >> 6) & 31, j = i & 63;
        const float* We = P.s[set].We;
        const float* Wa = P.s[set].Wa;
        float s = 0.0f;
        for (int h = 0; h < 64; h++) s += We[ce * 64 + h] * Wa[h * 64 + j];
        g_WeA[set][ce * 64 + j] = s;
    }
    for (int i = tid; i < 1024; i += stride) {
        int set = i >> 9, r = i & 511, hd = r >> 6, h = r & 63;
        const float* Wv = P.s[set].Wv;
        const float* Wo = P.s[set].Wo;
        float s = 0.0f;
        #pragma unroll
        for (int vc = 0; vc < 8; vc++)
            s += Wv[h * 64 + hd * 8 + vc] * Wo[hd * 8 + vc];
        g_Ut[set][hd * 64 + h] = s;
    }
    for (int i = tid; i < 512; i += stride) {
        int set = i >> 8, r = i & 255, hd = r >> 5, ce = r & 31;
        const float* Wv = P.s[set].Wv;
        const float* Wo = P.s[set].Wo;
        const float* We = P.s[set].We;
        float s = 0.0f;
        for (int h = 0; h < 64; h++) {
            float ut = 0.0f;
            #pragma unroll
            for (int vc = 0; vc < 8; vc++)
                ut += Wv[h * 64 + hd * 8 + vc] * Wo[hd * 8 + vc];
            s += ut * We[ce * 64 + h];
        }
        g_G[set][hd * 32 + ce] = s;
    }
    for (int i = tid; i < NN * 8; i += stride) g_expsum[i] = 0.0f;
    for (int i = tid; i < NN * 3; i += stride) out[i] = 0.0f;
}

// ---------------- per-node GEMM: A = X@(W@Wa) (3 parts), Y3 = X[1:4]@W ----------------
__global__ __launch_bounds__(256)
void k_node(const float* __restrict__ x, Par2 P) {
    __shared__ float Xs[64 * 20];           // [c][m] padded rows of 20
    int n = blockIdx.x;
    int tid = threadIdx.x;
    int bn = g_mask[n];

    for (int i = tid; i < 1024; i += 256) {
        int m = i >> 6, c = i & 63;
        Xs[c * 20 + m] = x[(size_t)n * 1024 + i];
    }
    __syncthreads();

    int mq = tid >> 6;          // 0..3
    int q  = tid & 63;
    int part = q >> 4;          // 0..3
    int h4 = (q & 15) * 4;

    if (part < 3) {
        const float* Wp = (part == 0) ? g_WA[0] : (part == 1) ? g_WA[1] : g_WTA[bn];
        u64 a0l = 0, a0h = 0, a1l = 0, a1h = 0, a2l = 0, a2h = 0, a3l = 0, a3h = 0;
        #pragma unroll 8
        for (int k = 0; k < 64; k++) {
            float4 xa = *(const float4*)&Xs[k * 20 + mq * 4];
            double2 wd = __ldg((const double2*)(Wp + k * 64 + h4));
            u64 w01 = d2l(wd.x), w23 = d2l(wd.y), xx;
            xx = pk2(xa.x); a0l = fma2(xx, w01, a0l); a0h = fma2(xx, w23, a0h);
            xx = pk2(xa.y); a1l = fma2(xx, w01, a1l); a1h = fma2(xx, w23, a1h);
            xx = pk2(xa.z); a2l = fma2(xx, w01, a2l); a2h = fma2(xx, w23, a2h);
            xx = pk2(xa.w); a3l = fma2(xx, w01, a3l); a3h = fma2(xx, w23, a3h);
        }
        double2* dst = (double2*)(g_A + (size_t)n * 3072 + part * 1024 + (mq * 4) * 64 + h4);
        dst[0]  = make_double2(__longlong_as_double(a0l), __longlong_as_double(a0h));
        dst[16] = make_double2(__longlong_as_double(a1l), __longlong_as_double(a1h));
        dst[32] = make_double2(__longlong_as_double(a2l), __longlong_as_double(a2h));
        dst[48] = make_double2(__longlong_as_double(a3l), __longlong_as_double(a3h));
    } else if (mq < 3) {
        const float* Wr = (mq == 0) ? P.s[0].Ws : (mq == 1) ? P.s[1].Ws : P.s[bn].Wt;
        u64 a0l = 0, a0h = 0, a1l = 0, a1h = 0, a2l = 0, a2h = 0;
        #pragma unroll 8
        for (int k = 0; k < 64; k++) {
            float4 xa = *(const float4*)&Xs[k * 20];   // m0..m3; use y,z,w
            double2 wd = __ldg((const double2*)(Wr + k * 64 + h4));
            u64 w01 = d2l(wd.x), w23 = d2l(wd.y), xx;
            xx = pk2(xa.y); a0l = fma2(xx, w01, a0l); a0h = fma2(xx, w23, a0h);
            xx = pk2(xa.z); a1l = fma2(xx, w01, a1l); a1h = fma2(xx, w23, a1h);
            xx = pk2(xa.w); a2l = fma2(xx, w01, a2l); a2h = fma2(xx, w23, a2h);
        }
        double2* dst = (double2*)(g_Y3 + (size_t)n * 576 + mq * 192 + h4);
        dst[0]  = make_double2(__longlong_as_double(a0l), __longlong_as_double(a0h));
        dst[16] = make_double2(__longlong_as_double(a1l), __longlong_as_double(a1h));
        dst[32] = make_double2(__longlong_as_double(a2l), __longlong_as_double(a2h));
    }
}

// ---------------- pass 1: logits + exp-sum (flat, 2 edges/warp, FFMA2) ----------------
__global__ __launch_bounds__(256)
void k_pass1(const int* __restrict__ zn, const float* __restrict__ dist,
             const int* __restrict__ ei, const float* __restrict__ wig, Par2 P) {
    __shared__ float s_WeA[2 * 2048];     // 16KB
    int tid = threadIdx.x;
    {
        const float* srcp = &g_WeA[0][0];
        for (int i = tid * 4; i < 4096; i += 1024)
            *(float4*)(s_WeA + i) = __ldg((const float4*)(srcp + i));
    }
    __syncthreads();

    int l  = tid & 31;
    int wid = tid >> 5;
    int le = l >> 4;
    int q  = l & 15;
    int eg = blockIdx.x * 16 + wid * 2 + le;

    int src = ei[eg], dst = ei[NE + eg];
    int b = g_mask[dst];
    const ParSet& pp = P.s[b];

    float dq = __ldg(wig + (size_t)eg * 256 + q);

    int zs = zn[src], zt = zn[dst];
    float dd = dist[eg];
    float z0 = dd * __ldg(pp.w_d + q)      + __ldg(pp.emb_s + zs * 32 + q)      + __ldg(pp.emb_t + zt * 32 + q);
    float z1 = dd * __ldg(pp.w_d + q + 16) + __ldg(pp.emb_s + zs * 32 + q + 16) + __ldg(pp.emb_t + zt * 32 + q + 16);
    float ev0 = z0 / (1.0f + __expf(-z0));
    float ev1 = z1 / (1.0f + __expf(-z1));

    const double2* As = (const double2*)(g_A + (size_t)src * 3072 + b * 1024);
    const double2* At = (const double2*)(g_A + (size_t)dst * 3072 + 2048);

    u64 acc01 = 0, acc23 = 0;
    #pragma unroll
    for (int n = 0; n < 16; n++) {
        float dn = __shfl_sync(0xffffffffu, dq, (le << 4) | n);
        double2 a1 = __ldg(As + n * 16 + q);
        double2 a2 = __ldg(At + n * 16 + q);
        u64 dp = pk2(dn);
        acc01 = fma2(dp, add2(d2l(a1.x), d2l(a2.x)), acc01);
        acc23 = fma2(dp, add2(d2l(a1.y), d2l(a2.y)), acc23);
    }
    const double2* sW = (const double2*)(s_WeA + b * 2048);
    #pragma unroll 8
    for (int ce = 0; ce < 32; ce++) {
        float evv = __shfl_sync(0xffffffffu, (ce < 16) ? ev0 : ev1, (le << 4) | (ce & 15));
        double2 w = sW[ce * 16 + q];
        u64 ep = pk2(evv);
        acc01 = fma2(ep, d2l(w.x), acc01);
        acc23 = fma2(ep, d2l(w.y), acc23);
    }
    float2 f01 = up2(acc01), f23 = up2(acc23);
    float4 vv = __ldg((const float4*)(pp.va + q * 4));
    float a0 = ((f01.x > 0.f) ? f01.x : 0.2f * f01.x) * vv.x;
    float a1 = ((f01.y > 0.f) ? f01.y : 0.2f * f01.y) * vv.y;
    float a2 = ((f23.x > 0.f) ? f23.x : 0.2f * f23.x) * vv.z;
    float a3 = ((f23.y > 0.f) ? f23.y : 0.2f * f23.y) * vv.w;
    float s = a0 + a1 + a2 + a3;
    s += __shfl_xor_sync(0xffffffffu, s, 1);
    if ((q & 1) == 0) {
        int head = q >> 1;
        float el = __expf(s);
        g_eexp[eg * 8 + head] = el;
        atomicAdd(&g_expsum[dst * 8 + head], el);
    }
}

// ---------------- pass 2: alpha, Ut/G-folded values, Y3 outputs (flat, FFMA2) ----------------
__global__ __launch_bounds__(256)
void k_pass2(const int* __restrict__ zn, const float* __restrict__ dist,
             const int* __restrict__ ei, const float* __restrict__ wig,
             Par2 P, float* __restrict__ out) {
    __shared__ float sUt[1024];     // 4KB  (both sets)
    __shared__ float sG[512];       // 2KB  (both sets)
    __shared__ float swd[64];
    int tid = threadIdx.x;
    for (int i = tid * 4; i < 1024; i += 1024)
        *(float4*)(sUt + i) = __ldg((const float4*)(&g_Ut[0][0] + i));
    for (int i = tid; i < 512; i += 256)
        sG[i] = (&g_G[0][0])[i];
    if (tid < 32) swd[tid] = __ldg(P.s[0].w_d + tid);
    if (tid >= 32 && tid < 64) swd[tid] = __ldg(P.s[1].w_d + tid - 32);
    __syncthreads();

    int l  = tid & 31;
    int wid = tid >> 5;
    int le = l >> 4;
    int q  = l & 15;
    int eg = blockIdx.x * 16 + wid * 2 + le;

    int src = ei[eg], dst = ei[NE + eg];
    int b = g_mask[dst];
    const ParSet& pp = P.s[b];

    // alpha on lanes q<8
    float al = 0.0f;
    if (q < 8)
        al = g_eexp[eg * 8 + q] / (g_expsum[dst * 8 + q] + 1e-9f);

    // p = sum_hd Ut[b][hd]*alpha[hd]; pinj weights via G
    const double2* sU2 = (const double2*)(sUt + b * 512);
    u64 p01 = 0, p23 = 0;
    float w0 = 0.0f, w1 = 0.0f;
    #pragma unroll
    for (int hd = 0; hd < 8; hd++) {
        float av = __shfl_sync(0xffffffffu, al, (le << 4) | hd);
        double2 u = sU2[hd * 16 + q];
        u64 ap = pk2(av);
        p01 = fma2(ap, d2l(u.x), p01);
        p23 = fma2(ap, d2l(u.y), p23);
        w0 += av * sG[b * 256 + hd * 32 + q];
        w1 += av * sG[b * 256 + hd * 32 + q + 16];
    }

    // edge scalars
    int zs = zn[src], zt = zn[dst];
    float dd = __ldg(dist + eg);
    float z0 = dd * swd[b * 32 + q]      + __ldg(pp.emb_s + zs * 32 + q)      + __ldg(pp.emb_t + zt * 32 + q);
    float z1 = dd * swd[b * 32 + q + 16] + __ldg(pp.emb_s + zs * 32 + q + 16) + __ldg(pp.emb_t + zt * 32 + q + 16);
    float ev0 = z0 / (1.0f + __expf(-z0));
    float ev1 = z1 / (1.0f + __expf(-z1));
    float pinj = ev0 * w0 + ev1 * w1;

    // output rows via Y3 (f32x2 dot products)
    const double2* Ys = (const double2*)(g_Y3 + (size_t)src * 576 + b * 192);
    const double2* Yt = (const double2*)(g_Y3 + (size_t)dst * 576 + 384);
    float o[3];
    #pragma unroll
    for (int r = 0; r < 3; r++) {
        double2 y = __ldg(Ys + r * 16 + q);
        double2 t = __ldg(Yt + r * 16 + q);
        u64 acc = fma2(p01, add2(d2l(y.x), d2l(t.x)),
                  fma2(p23, add2(d2l(y.y), d2l(t.y)), 0ULL));
        float2 f = up2(acc);
        o[r] = f.x + f.y;
    }
    float o0 = o[0], o1 = o[1], o2 = o[2];

    // reduce 4 scalars over 16-lane group
    #pragma unroll
    for (int off = 8; off; off >>= 1) {
        o0   += __shfl_down_sync(0xffffffffu, o0, off, 16);
        o1   += __shfl_down_sync(0xffffffffu, o1, off, 16);
        o2   += __shfl_down_sync(0xffffffffu, o2, off, 16);
        pinj += __shfl_down_sync(0xffffffffu, pinj, off, 16);
    }
    if (q == 0) {
        float d1 = __ldg(wig + (size_t)eg * 256 + 1);
        float d2 = __ldg(wig + (size_t)eg * 256 + 2);
        float d3 = __ldg(wig + (size_t)eg * 256 + 3);
        atomicAdd(&out[dst * 3 + 0], o0 + pinj * d1);
        atomicAdd(&out[dst * 3 + 1], o1 + pinj * d2);
        atomicAdd(&out[dst * 3 + 2], o2 + pinj * d3);
    }
}

extern "C" void kernel_launch(void* const* d_in, const int* in_sizes, int n_in,
                              void* d_out, int out_size) {
    const float* x    = (const float*)d_in[0];
    const int*   zn   = (const int*)d_in[1];
    const float* dist = (const float*)d_in[2];
    const int*   ei   = (const int*)d_in[3];
    const void*  nm   = d_in[4];
    const float* wig  = (const float*)d_in[5];

    Par2 P;
    for (int s = 0; s < 2; s++) {
        int base = 6 + s * 10;
        P.s[s].emb_s = (const float*)d_in[base + 0];
        P.s[s].emb_t = (const float*)d_in[base + 1];
        P.s[s].w_d   = (const float*)d_in[base + 2];
        P.s[s].We    = (const float*)d_in[base + 3];
        P.s[s].Ws    = (const float*)d_in[base + 4];
        P.s[s].Wt    = (const float*)d_in[base + 5];
        P.s[s].Wa    = (const float*)d_in[base + 6];
        P.s[s].va    = (const float*)d_in[base + 7];
        P.s[s].Wv    = (const float*)d_in[base + 8];
        P.s[s].Wo    = (const float*)d_in[base + 9];
    }
    float* out = (float*)d_out;

    k_small<<<65, 256>>>(P, nm, out);
    k_node<<<NN, 256>>>(x, P);
    k_pass1<<<NE / 16, 256>>>(zn, dist, ei, wig, P);
    k_pass2<<<NE / 16, 256>>>(zn, dist, ei, wig, P, out);
}

// round 14
// speedup vs baseline: 1.0272x; 1.0272x over previous
#include <cuda_runtime.h>
#include <math.h>

#define NN 4000
#define NE 60000

typedef unsigned long long u64;

// ---------------- scratch ----------------
__device__ float g_WA[2][4096];   // Ws@Wa per set
__device__ float g_WTA[2][4096];  // Wt@Wa per set
__device__ float g_WeA[2][2048];  // We@Wa per set
__device__ float g_Ut[2][512];    // [set][hd][h]  (Wv·Wo folded)
__device__ float g_G[2][256];     // [set][hd][ce] = Ut @ We^T
__device__ float g_Urs[2][64];    // rowsum of Ut over hd  (softmax-sum fold)
__device__ float g_A[NN * 3072];  // [n][part][16][64]; part 0=As set0,1=As set1,2=At own
__device__ float g_Y3[NN * 576];  // [n][part][3][64]; parts 0,1 = Ys per set (Yt folded away)
__device__ float g_eexp[NE * 8];  // exp(logit)
__device__ float g_expsum[NN * 8];
__device__ int   g_mask[NN];

struct ParSet {
    const float *emb_s, *emb_t, *w_d, *We, *Ws, *Wt, *Wa, *va, *Wv, *Wo;
};
struct Par2 { ParSet s[2]; };

// ---------------- packed f32x2 helpers ----------------
__device__ __forceinline__ u64 pk2(float a) {
    u64 r;
    asm("mov.b64 %0, {%1, %1};" : "=l"(r) : "r"(__float_as_uint(a)));
    return r;
}
__device__ __forceinline__ u64 fma2(u64 a, u64 b, u64 c) {
    u64 d;
    asm("fma.rn.f32x2 %0, %1, %2, %3;" : "=l"(d) : "l"(a), "l"(b), "l"(c));
    return d;
}
__device__ __forceinline__ u64 d2l(double d) { return __double_as_longlong(d); }
__device__ __forceinline__ float2 up2(u64 v) {
    float2 f;
    asm("mov.b64 {%0, %1}, %2;" : "=f"(f.x), "=f"(f.y) : "l"(v));
    return f;
}

// ---------------- weight folds + zeroing + mask sniff (block 64) ----------------
__global__ void k_small(Par2 P, const void* nm, float* out) {
    if (blockIdx.x == 64) {
        __shared__ int s_max, s_s1;
        if (threadIdx.x == 0) { s_max = 0; s_s1 = 0; }
        __syncthreads();
        const unsigned char* bp = (const unsigned char*)nm;
        int lm = 0, ls = 0;
        for (int i = threadIdx.x; i < NN; i += 256) {
            int v = bp[i];
            if (v > lm) lm = v;
            if ((i & 3) == 1) ls += v;
        }
        atomicMax(&s_max, lm);
        atomicAdd(&s_s1, ls);
        __syncthreads();
        int mode = (s_max > 1) ? 2 : (s_s1 > 0 ? 0 : 1);
        for (int n = threadIdx.x; n < NN; n += 256) {
            int v;
            if (mode == 0)      v = (bp[n] != 0);
            else if (mode == 1) v = (((const int*)nm)[n] != 0);
            else                v = (((const float*)nm)[n] != 0.0f);
            g_mask[n] = v;
        }
        return;
    }
    int tid = blockIdx.x * blockDim.x + threadIdx.x;
    const int stride = 64 * 256;
    for (int i = tid; i < 16384; i += stride) {
        int mat = i >> 12, c = (i >> 6) & 63, j = i & 63;
        int set = mat & 1;
        const float* W  = (mat < 2) ? P.s[set].Ws : P.s[set].Wt;
        const float* Wa = P.s[set].Wa;
        float s = 0.0f;
        for (int h = 0; h < 64; h++) s += W[c * 64 + h] * Wa[h * 64 + j];
        if (mat < 2) g_WA[set][c * 64 + j] = s;
        else         g_WTA[set][c * 64 + j] = s;
    }
    for (int i = tid; i < 4096; i += stride) {
        int set = i >> 11, ce = (i >> 6) & 31, j = i & 63;
        const float* We = P.s[set].We;
        const float* Wa = P.s[set].Wa;
        float s = 0.0f;
        for (int h = 0; h < 64; h++) s += We[ce * 64 + h] * Wa[h * 64 + j];
        g_WeA[set][ce * 64 + j] = s;
    }
    for (int i = tid; i < 1024; i += stride) {
        int set = i >> 9, r = i & 511, hd = r >> 6, h = r & 63;
        const float* Wv = P.s[set].Wv;
        const float* Wo = P.s[set].Wo;
        float s = 0.0f;
        #pragma unroll
        for (int vc = 0; vc < 8; vc++)
            s += Wv[h * 64 + hd * 8 + vc] * Wo[hd * 8 + vc];
        g_Ut[set][hd * 64 + h] = s;
    }
    for (int i = tid; i < 512; i += stride) {
        int set = i >> 8, r = i & 255, hd = r >> 5, ce = r & 31;
        const float* Wv = P.s[set].Wv;
        const float* Wo = P.s[set].Wo;
        const float* We = P.s[set].We;
        float s = 0.0f;
        for (int h = 0; h < 64; h++) {
            float ut = 0.0f;
            #pragma unroll
            for (int vc = 0; vc < 8; vc++)
                ut += Wv[h * 64 + hd * 8 + vc] * Wo[hd * 8 + vc];
            s += ut * We[ce * 64 + h];
        }
        g_G[set][hd * 32 + ce] = s;
    }
    // Urs[set][h] = sum_hd Ut[set][hd][h] = sum_j Wv[h][j]*Wo[j]
    for (int i = tid; i < 128; i += stride) {
        int set = i >> 6, h = i & 63;
        const float* Wv = P.s[set].Wv;
        const float* Wo = P.s[set].Wo;
        float s = 0.0f;
        for (int j = 0; j < 64; j++) s += Wv[h * 64 + j] * Wo[j];
        g_Urs[set][h] = s;
    }
    for (int i = tid; i < NN * 8; i += stride) g_expsum[i] = 0.0f;
    for (int i = tid; i < NN * 3; i += stride) out[i] = 0.0f;
}

// ---------------- per-node GEMM (divergence-free 384-thread layout) ----------------
// warps 0-5 (192 thr): A = X@(W@Wa), 3 parts x 4 m-quads x 16 j-lanes
// warps 6-11 (192 thr): Y3 rows (9 real units + 3 dummy pad units) + Yt node-term
__global__ __launch_bounds__(384)
void k_node(const float* __restrict__ x, Par2 P, float* __restrict__ out) {
    __shared__ float Xs[64 * 20];           // [c][m] padded rows of 20
    int n = blockIdx.x;
    int tid = threadIdx.x;
    int bn = g_mask[n];

    for (int i = tid; i < 1024; i += 384) {
        int m = i >> 6, c = i & 63;
        Xs[c * 20 + m] = x[(size_t)n * 1024 + i];
    }
    __syncthreads();

    if (tid < 192) {
        int part = tid >> 6;            // 0..2 (uniform per warp-pair)
        int mq   = (tid >> 4) & 3;
        int j4   = (tid & 15) * 4;
        const float* Wp = (part == 0) ? g_WA[0] : (part == 1) ? g_WA[1] : g_WTA[bn];
        u64 a0l = 0, a0h = 0, a1l = 0, a1h = 0, a2l = 0, a2h = 0, a3l = 0, a3h = 0;
        #pragma unroll 8
        for (int k = 0; k < 64; k++) {
            float4 xa = *(const float4*)&Xs[k * 20 + mq * 4];
            double2 wd = __ldg((const double2*)(Wp + k * 64 + j4));
            u64 w01 = d2l(wd.x), w23 = d2l(wd.y), xx;
            xx = pk2(xa.x); a0l = fma2(xx, w01, a0l); a0h = fma2(xx, w23, a0h);
            xx = pk2(xa.y); a1l = fma2(xx, w01, a1l); a1h = fma2(xx, w23, a1h);
            xx = pk2(xa.z); a2l = fma2(xx, w01, a2l); a2h = fma2(xx, w23, a2h);
            xx = pk2(xa.w); a3l = fma2(xx, w01, a3l); a3h = fma2(xx, w23, a3h);
        }
        double2* dst = (double2*)(g_A + (size_t)n * 3072 + part * 1024 + (mq * 4) * 64 + j4);
        dst[0]  = make_double2(__longlong_as_double(a0l), __longlong_as_double(a0h));
        dst[16] = make_double2(__longlong_as_double(a1l), __longlong_as_double(a1h));
        dst[32] = make_double2(__longlong_as_double(a2l), __longlong_as_double(a2h));
        dst[48] = make_double2(__longlong_as_double(a3l), __longlong_as_double(a3h));
    } else {
        int u    = tid - 192;
        int unit = u >> 4;              // 0..11 (9 real, 3 dummy pad)
        int j4   = (u & 15) * 4;
        bool real = unit < 9;
        int mat = real ? unit / 3 : 2;  // 0=Ys set0, 1=Ys set1, 2=Yt own
        int rr  = real ? unit % 3 : unit - 9;
        const float* Wr = (mat == 0) ? P.s[0].Ws : (mat == 1) ? P.s[1].Ws : P.s[bn].Wt;
        u64 al = 0, ah = 0;
        #pragma unroll 8
        for (int k = 0; k < 64; k++) {
            float xv = Xs[k * 20 + 1 + rr];
            double2 wd = __ldg((const double2*)(Wr + k * 64 + j4));
            u64 xx = pk2(xv);
            al = fma2(xx, d2l(wd.x), al);
            ah = fma2(xx, d2l(wd.y), ah);
        }
        if (mat < 2) {
            // warps 6-8: uniform store path
            *(double2*)(g_Y3 + (size_t)n * 576 + mat * 192 + rr * 64 + j4) =
                make_double2(__longlong_as_double(al), __longlong_as_double(ah));
        } else {
            // warps 9-11: uniform node-term path (dummy units compute, don't store)
            float4 ur = __ldg((const float4*)(&g_Urs[bn][j4]));
            float2 f0 = up2(al), f1 = up2(ah);
            float v = f0.x * ur.x + f0.y * ur.y + f1.x * ur.z + f1.y * ur.w;
            v += __shfl_down_sync(0xffffffffu, v, 8, 16);
            v += __shfl_down_sync(0xffffffffu, v, 4, 16);
            v += __shfl_down_sync(0xffffffffu, v, 2, 16);
            v += __shfl_down_sync(0xffffffffu, v, 1, 16);
            if (real && (u & 15) == 0) out[n * 3 + rr] = v;
        }
    }
}

// ---------------- pass 1: logits + exp-sum (flat, 2 edges/warp, scalar) ----------------
__global__ __launch_bounds__(256)
void k_pass1(const int* __restrict__ zn, const float* __restrict__ dist,
             const int* __restrict__ ei, const float* __restrict__ wig, Par2 P) {
    __shared__ float s_WeA[2 * 2048];     // 16KB
    int tid = threadIdx.x;
    {
        const float* srcp = &g_WeA[0][0];
        for (int i = tid * 4; i < 4096; i += 1024)
            *(float4*)(s_WeA + i) = __ldg((const float4*)(srcp + i));
    }
    __syncthreads();

    int l  = tid & 31;
    int wid = tid >> 5;
    int le = l >> 4;
    int q  = l & 15;
    int eg = blockIdx.x * 16 + wid * 2 + le;

    int src = ei[eg], dst = ei[NE + eg];
    int b = g_mask[dst];
    const ParSet& pp = P.s[b];

    float dq = __ldg(wig + (size_t)eg * 256 + q);

    int zs = zn[src], zt = zn[dst];
    float dd = dist[eg];
    float z0 = dd * __ldg(pp.w_d + q)      + __ldg(pp.emb_s + zs * 32 + q)      + __ldg(pp.emb_t + zt * 32 + q);
    float z1 = dd * __ldg(pp.w_d + q + 16) + __ldg(pp.emb_s + zs * 32 + q + 16) + __ldg(pp.emb_t + zt * 32 + q + 16);
    float ev0 = z0 / (1.0f + __expf(-z0));
    float ev1 = z1 / (1.0f + __expf(-z1));

    const float4* As = (const float4*)(g_A + (size_t)src * 3072 + b * 1024);
    const float4* At = (const float4*)(g_A + (size_t)dst * 3072 + 2048);

    float4 acc = {0, 0, 0, 0};
    #pragma unroll
    for (int n = 0; n < 16; n++) {
        float dn = __shfl_sync(0xffffffffu, dq, (le << 4) | n);
        float4 a1 = __ldg(As + n * 16 + q);
        float4 a2 = __ldg(At + n * 16 + q);
        acc.x += dn * (a1.x + a2.x);
        acc.y += dn * (a1.y + a2.y);
        acc.z += dn * (a1.z + a2.z);
        acc.w += dn * (a1.w + a2.w);
    }
    const float* sW = s_WeA + b * 2048;
    #pragma unroll 8
    for (int ce = 0; ce < 32; ce++) {
        float evv = __shfl_sync(0xffffffffu, (ce < 16) ? ev0 : ev1, (le << 4) | (ce & 15));
        float4 w = *(const float4*)(sW + ce * 64 + q * 4);
        acc.x += evv * w.x; acc.y += evv * w.y; acc.z += evv * w.z; acc.w += evv * w.w;
    }
    float4 vv = __ldg((const float4*)(pp.va + q * 4));
    float a0 = ((acc.x > 0.f) ? acc.x : 0.2f * acc.x) * vv.x;
    float a1 = ((acc.y > 0.f) ? acc.y : 0.2f * acc.y) * vv.y;
    float a2 = ((acc.z > 0.f) ? acc.z : 0.2f * acc.z) * vv.z;
    float a3 = ((acc.w > 0.f) ? acc.w : 0.2f * acc.w) * vv.w;
    float s = a0 + a1 + a2 + a3;
    s += __shfl_xor_sync(0xffffffffu, s, 1);
    if ((q & 1) == 0) {
        int head = q >> 1;
        float el = __expf(s);
        g_eexp[eg * 8 + head] = el;
        atomicAdd(&g_expsum[dst * 8 + head], el);
    }
}

// ---------------- pass 2: alpha, Ut/G-folded values, Ys-only outputs ----------------
__global__ __launch_bounds__(256)
void k_pass2(const int* __restrict__ zn, const float* __restrict__ dist,
             const int* __restrict__ ei, const float* __restrict__ wig,
             Par2 P, float* __restrict__ out) {
    __shared__ float sUt[1024];     // 4KB (both sets)
    __shared__ float sG[512];       // 2KB (both sets)
    __shared__ float swd[64];
    int tid = threadIdx.x;
    for (int i = tid * 4; i < 1024; i += 1024)
        *(float4*)(sUt + i) = __ldg((const float4*)(&g_Ut[0][0] + i));
    for (int i = tid; i < 512; i += 256)
        sG[i] = (&g_G[0][0])[i];
    if (tid < 32) swd[tid] = __ldg(P.s[0].w_d + tid);
    if (tid >= 32 && tid < 64) swd[tid] = __ldg(P.s[1].w_d + tid - 32);
    __syncthreads();

    int l  = tid & 31;
    int wid = tid >> 5;
    int le = l >> 4;
    int q  = l & 15;
    int eg = blockIdx.x * 16 + wid * 2 + le;

    int src = ei[eg], dst = ei[NE + eg];
    int b = g_mask[dst];
    const ParSet& pp = P.s[b];

    // alpha on lanes q<8
    float al = 0.0f;
    if (q < 8)
        al = g_eexp[eg * 8 + q] / (g_expsum[dst * 8 + q] + 1e-9f);

    // p = sum_hd Ut[b][hd]*alpha[hd]; pinj weights via G
    float4 p = {0, 0, 0, 0};
    float w0 = 0.0f, w1 = 0.0f;
    #pragma unroll
    for (int hd = 0; hd < 8; hd++) {
        float av = __shfl_sync(0xffffffffu, al, (le << 4) | hd);
        float4 u = *(const float4*)(sUt + b * 512 + hd * 64 + q * 4);
        p.x += av * u.x; p.y += av * u.y; p.z += av * u.z; p.w += av * u.w;
        w0 += av * sG[b * 256 + hd * 32 + q];
        w1 += av * sG[b * 256 + hd * 32 + q + 16];
    }

    // edge scalars
    int zs = zn[src], zt = zn[dst];
    float dd = __ldg(dist + eg);
    float z0 = dd * swd[b * 32 + q]      + __ldg(pp.emb_s + zs * 32 + q)      + __ldg(pp.emb_t + zt * 32 + q);
    float z1 = dd * swd[b * 32 + q + 16] + __ldg(pp.emb_s + zs * 32 + q + 16) + __ldg(pp.emb_t + zt * 32 + q + 16);
    float ev0 = z0 / (1.0f + __expf(-z0));
    float ev1 = z1 / (1.0f + __expf(-z1));
    float pinj = ev0 * w0 + ev1 * w1;

    // output rows: src side only (Yt term folded into k_node via sum(alpha)=1)
    const float4* Ys = (const float4*)(g_Y3 + (size_t)src * 576 + b * 192);
    float o0, o1, o2;
    {
        float4 y;
        y = __ldg(Ys + q);       o0 = p.x * y.x + p.y * y.y + p.z * y.z + p.w * y.w;
        y = __ldg(Ys + 16 + q);  o1 = p.x * y.x + p.y * y.y + p.z * y.z + p.w * y.w;
        y = __ldg(Ys + 32 + q);  o2 = p.x * y.x + p.y * y.y + p.z * y.z + p.w * y.w;
    }

    // reduce 4 scalars over 16-lane group
    #pragma unroll
    for (int off = 8; off; off >>= 1) {
        o0   += __shfl_down_sync(0xffffffffu, o0, off, 16);
        o1   += __shfl_down_sync(0xffffffffu, o1, off, 16);
        o2   += __shfl_down_sync(0xffffffffu, o2, off, 16);
        pinj += __shfl_down_sync(0xffffffffu, pinj, off, 16);
    }
    if (q == 0) {
        float d1 = __ldg(wig + (size_t)eg * 256 + 1);
        float d2 = __ldg(wig + (size_t)eg * 256 + 2);
        float d3 = __ldg(wig + (size_t)eg * 256 + 3);
        atomicAdd(&out[dst * 3 + 0], o0 + pinj * d1);
        atomicAdd(&out[dst * 3 + 1], o1 + pinj * d2);
        atomicAdd(&out[dst * 3 + 2], o2 + pinj * d3);
    }
}

extern "C" void kernel_launch(void* const* d_in, const int* in_sizes, int n_in,
                              void* d_out, int out_size) {
    const float* x    = (const float*)d_in[0];
    const int*   zn   = (const int*)d_in[1];
    const float* dist = (const float*)d_in[2];
    const int*   ei   = (const int*)d_in[3];
    const void*  nm   = d_in[4];
    const float* wig  = (const float*)d_in[5];

    Par2 P;
    for (int s = 0; s < 2; s++) {
        int base = 6 + s * 10;
        P.s[s].emb_s = (const float*)d_in[base + 0];
        P.s[s].emb_t = (const float*)d_in[base + 1];
        P.s[s].w_d   = (const float*)d_in[base + 2];
        P.s[s].We    = (const float*)d_in[base + 3];
        P.s[s].Ws    = (const float*)d_in[base + 4];
        P.s[s].Wt    = (const float*)d_in[base + 5];
        P.s[s].Wa    = (const float*)d_in[base + 6];
        P.s[s].va    = (const float*)d_in[base + 7];
        P.s[s].Wv    = (const float*)d_in[base + 8];
        P.s[s].Wo    = (const float*)d_in[base + 9];
    }
    float* out = (float*)d_out;

    k_small<<<65, 256>>>(P, nm, out);
    k_node<<<NN, 384>>>(x, P, out);
    k_pass1<<<NE / 16, 256>>>(zn, dist, ei, wig, P);
    k_pass2<<<NE / 16, 256>>>(zn, dist, ei, wig, P, out);
}